// round 8
// baseline (speedup 1.0000x reference)
#include <cuda_runtime.h>
#include <cuda_bf16.h>

// Problem constants
#define BB 8
#define LL 8192
#define DD 512
#define SF 4
#define RR 32               // rows per chunk
#define CH (LL / RR)        // 256 chunks per batch
#define NW 4                // warp-slices per chunk (d4 split)
#define UNITS (BB * CH * NW)// 8192 warp work-units
#define GRID (BB * CH)      // 2048 blocks x 128 threads = 8192 warps
#define OUT_L (LL / SF)     // 2048
#define D4 (DD / 4)         // 128 float4 lanes
#define OUTG (RR / SF)      // 8 output rows per chunk

// Lookback state (8 MB value scratch, L2-resident)
__device__ float g_agg[BB][CH][DD];     // per-chunk aggregate   (flag>=1)
__device__ float g_inc[BB][CH][DD];     // per-chunk inclusive   (flag==2)
__device__ int g_flag[BB][CH][NW];      // 0=empty 1=agg 2=inclusive, per warp-slice
__device__ unsigned g_ticket;

__device__ __forceinline__ int ld_acq(const int* p) {
    int v;
    asm volatile("ld.acquire.gpu.s32 %0, [%1];" : "=r"(v) : "l"(p) : "memory");
    return v;
}

__global__ void k_reset() {
    int i = blockIdx.x * blockDim.x + threadIdx.x;
    if (i < BB * CH * NW) ((int*)g_flag)[i] = 0;
    if (i == 0) g_ticket = 0u;
}

__global__ __launch_bounds__(128, 8) void k_main(const float* __restrict__ x,
                                                 float* __restrict__ out) {
    const int lane = threadIdx.x & 31;

    // Per-warp ticket: acquisition order == scheduling order -> progress
    unsigned t;
    if (lane == 0) t = atomicAdd(&g_ticket, 1u);
    t = __shfl_sync(0xFFFFFFFFu, t, 0);
    const int b = (int)(t / (CH * NW));
    const int r = (int)(t % (CH * NW));
    const int c = r / NW;
    const int w = r % NW;
    const int d4 = w * 32 + lane;        // this warp's d4 slice

    // ── Phase A: local chunk scan; partials stay in registers ──
    const float4* xp = reinterpret_cast<const float4*>(
        x + ((size_t)b * LL + (size_t)c * RR) * DD) + d4;
    float4 acc = make_float4(0.f, 0.f, 0.f, 0.f);
    float4 outp[OUTG];
#pragma unroll
    for (int g = 0; g < OUTG; ++g) {
        float4 v0 = __ldcs(xp + (size_t)(g * SF + 0) * D4);
        float4 v1 = __ldcs(xp + (size_t)(g * SF + 1) * D4);
        float4 v2 = __ldcs(xp + (size_t)(g * SF + 2) * D4);
        float4 v3 = __ldcs(xp + (size_t)(g * SF + 3) * D4);
        acc.x += (v0.x + v1.x) + (v2.x + v3.x);
        acc.y += (v0.y + v1.y) + (v2.y + v3.y);
        acc.z += (v0.z + v1.z) + (v2.z + v3.z);
        acc.w += (v0.w + v1.w) + (v2.w + v3.w);
        outp[g] = acc;
    }

    // ── Phase B: publish aggregate slice (warp-scope, no block sync) ──
    if (c > 0 && c < CH - 1) {
        reinterpret_cast<float4*>(g_agg[b][c])[d4] = acc;
        __threadfence();                 // each lane orders its own store
        __syncwarp();
        if (lane == 0) atomicExch(&g_flag[b][c][w], 1);
    }

    // ── Phase C: warp-autonomous windowed lookback ──
    float4 run = make_float4(0.f, 0.f, 0.f, 0.f);
    if (c > 0) {
        int p = c - 1;                   // highest unconsumed predecessor
        for (;;) {
            const int W = (p + 1 < 32) ? (p + 1) : 32;
            int f = 0;
            if (lane < W) {
                const int* fp = &g_flag[b][p - lane][w];
                f = ld_acq(fp);
                while (f == 0) { __nanosleep(64); f = ld_acq(fp); }
            }
            const unsigned done_mask = __ballot_sync(0xFFFFFFFFu, f == 2);
            int limit, found;
            if (done_mask) { limit = __ffs(done_mask) - 1; found = 1; }
            else           { limit = W - 1;               found = 0; }
            // sum up to 32 independent 512B-coalesced vectors from L2
            for (int j = 0; j <= limit; ++j) {
                const int q = p - j;
                const float* src = (found && j == limit) ? g_inc[b][q] : g_agg[b][q];
                float4 v = reinterpret_cast<const float4*>(src)[d4];
                run.x += v.x; run.y += v.y; run.z += v.z; run.w += v.w;
            }
            if (found) break;
            p -= W;                      // chunk 0 publishes flag==2, so p>=0
        }
    }

    // ── Phase D: publish inclusive slice (warp-scope) ──
    if (c < CH - 1) {
        float4 inc = make_float4(acc.x + run.x, acc.y + run.y,
                                 acc.z + run.z, acc.w + run.w);
        reinterpret_cast<float4*>(g_inc[b][c])[d4] = inc;
        __threadfence();
        __syncwarp();
        if (lane == 0) atomicExch(&g_flag[b][c][w], 2);
    }

    // ── Phase E: emit final scaled means (single write of out) ──
    float4* op = reinterpret_cast<float4*>(
        out + ((size_t)b * OUT_L + (size_t)c * OUTG) * DD) + d4;
#pragma unroll
    for (int g = 0; g < OUTG; ++g) {
        const float inv = 1.0f / (float)(c * RR + g * SF + SF);
        float4 o;
        o.x = (outp[g].x + run.x) * inv;
        o.y = (outp[g].y + run.y) * inv;
        o.z = (outp[g].z + run.z) * inv;
        o.w = (outp[g].w + run.w) * inv;
        op[(size_t)g * D4] = o;
    }
}

extern "C" void kernel_launch(void* const* d_in, const int* in_sizes, int n_in,
                              void* d_out, int out_size) {
    const float* x = (const float*)d_in[0];
    float* out = (float*)d_out;

    k_reset<<<(UNITS + 255) / 256, 256>>>();
    k_main<<<GRID, 128>>>(x, out);
}

// round 9
// speedup vs baseline: 1.1334x; 1.1334x over previous
#include <cuda_runtime.h>
#include <cuda_bf16.h>

// Problem constants
#define BB 8
#define LL 8192
#define DD 512
#define SF 4
#define RR 32                 // rows per chunk
#define CH (LL / RR)          // 256 chunks per batch
#define NCHUNK (BB * CH)      // 2048 total chunks
#define OUT_L (LL / SF)       // 2048
#define D4 (DD / 4)           // 128 float4 lanes
#define OUTG (RR / SF)        // 8 output rows per chunk
#define NSUP 16               // supers per batch (16 chunks each)
#define SUPC (CH / NSUP)      // 16 chunks per super
#define GRIDN 1024            // persistent grid (all co-resident @ 8 blocks/SM)
#define CPB (NCHUNK / GRIDN)  // 2 chunks per block

// Scratch (L2-resident)
__device__ float g_part[BB][CH][DD];        // per-chunk aggregates (4 MB)
__device__ float g_sup[BB][NSUP][DD];       // per-super sums (256 KB)
__device__ unsigned g_bar[2];               // barrier arrive counters
__device__ unsigned g_rel[2];               // barrier release flags

__device__ __forceinline__ unsigned ld_acq_u(const unsigned* p) {
    unsigned v;
    asm volatile("ld.acquire.gpu.u32 %0, [%1];" : "=r"(v) : "l"(p) : "memory");
    return v;
}

__global__ void k_reset() {
    if (threadIdx.x < 2) { g_bar[threadIdx.x] = 0u; g_rel[threadIdx.x] = 0u; }
}

// Grid barrier: safe because all GRIDN blocks are co-resident (launch_bounds).
__device__ __forceinline__ void gsync(int i) {
    __syncthreads();
    if (threadIdx.x == 0) {
        __threadfence();                       // release my prior writes
        unsigned v = atomicAdd(&g_bar[i], 1u);
        if (v == GRIDN - 1) {
            atomicExch(&g_rel[i], 1u);
        } else {
            while (ld_acq_u(&g_rel[i]) == 0u) __nanosleep(64);
        }
    }
    __syncthreads();
    __threadfence();                           // acquire others' writes
}

__global__ __launch_bounds__(128, 8) void k_all(const float* __restrict__ x,
                                                float* __restrict__ out) {
    const int tid = threadIdx.x;
    const int d4 = tid;

    // ── Phase A: per-chunk local scan; unscaled partials -> out, agg -> g_part ──
#pragma unroll
    for (int u = 0; u < CPB; ++u) {
        const int t = blockIdx.x * CPB + u;    // chunk id 0..2047
        const int b = t >> 8;                  // t / CH
        const int c = t & (CH - 1);            // t % CH
        const float4* xp = reinterpret_cast<const float4*>(
            x + ((size_t)b * LL + (size_t)c * RR) * DD) + d4;
        float4* op = reinterpret_cast<float4*>(
            out + ((size_t)b * OUT_L + (size_t)c * OUTG) * DD) + d4;

        float4 acc = make_float4(0.f, 0.f, 0.f, 0.f);
#pragma unroll
        for (int g = 0; g < OUTG; ++g) {
            float4 v0 = __ldcs(xp + (size_t)(g * SF + 0) * D4);
            float4 v1 = __ldcs(xp + (size_t)(g * SF + 1) * D4);
            float4 v2 = __ldcs(xp + (size_t)(g * SF + 2) * D4);
            float4 v3 = __ldcs(xp + (size_t)(g * SF + 3) * D4);
            acc.x += (v0.x + v1.x) + (v2.x + v3.x);
            acc.y += (v0.y + v1.y) + (v2.y + v3.y);
            acc.z += (v0.z + v1.z) + (v2.z + v3.z);
            acc.w += (v0.w + v1.w) + (v2.w + v3.w);
            op[(size_t)g * D4] = acc;          // unscaled partial prefix
        }
        reinterpret_cast<float4*>(g_part[b][c])[d4] = acc;
    }

    gsync(0);

    // ── Phase B: super sums (blocks 0..127 active; others pass through) ──
    if (blockIdx.x < BB * NSUP) {
        const int b = blockIdx.x >> 4;
        const int s = blockIdx.x & (NSUP - 1);
        float4 sum = make_float4(0.f, 0.f, 0.f, 0.f);
#pragma unroll
        for (int k = 0; k < SUPC; ++k) {
            float4 v = reinterpret_cast<const float4*>(g_part[b][s * SUPC + k])[d4];
            sum.x += v.x; sum.y += v.y; sum.z += v.z; sum.w += v.w;
        }
        reinterpret_cast<float4*>(g_sup[b][s])[d4] = sum;
    }

    gsync(1);

    // ── Phase C: per-chunk base from hierarchy (L2-hot), fix out in place ──
#pragma unroll
    for (int u = 0; u < CPB; ++u) {
        const int t = blockIdx.x * CPB + u;
        const int b = t >> 8;
        const int c = t & (CH - 1);
        const int s = c >> 4;                  // full supers before c
        const int nin = c & (SUPC - 1);        // chunks before c within super

        float4 base = make_float4(0.f, 0.f, 0.f, 0.f);
        for (int j = 0; j < s; ++j) {
            float4 v = reinterpret_cast<const float4*>(g_sup[b][j])[d4];
            base.x += v.x; base.y += v.y; base.z += v.z; base.w += v.w;
        }
        for (int j = 0; j < nin; ++j) {
            float4 v = reinterpret_cast<const float4*>(g_part[b][s * SUPC + j])[d4];
            base.x += v.x; base.y += v.y; base.z += v.z; base.w += v.w;
        }

        float4* op = reinterpret_cast<float4*>(
            out + ((size_t)b * OUT_L + (size_t)c * OUTG) * DD) + d4;
#pragma unroll
        for (int g = 0; g < OUTG; ++g) {
            const float inv = 1.0f / (float)(c * RR + g * SF + SF);
            float4 v = op[(size_t)g * D4];
            v.x = (v.x + base.x) * inv;
            v.y = (v.y + base.y) * inv;
            v.z = (v.z + base.z) * inv;
            v.w = (v.w + base.w) * inv;
            op[(size_t)g * D4] = v;
        }
    }
}

extern "C" void kernel_launch(void* const* d_in, const int* in_sizes, int n_in,
                              void* d_out, int out_size) {
    const float* x = (const float*)d_in[0];
    float* out = (float*)d_out;

    k_reset<<<1, 32>>>();
    k_all<<<GRIDN, 128>>>(x, out);
}